// round 8
// baseline (speedup 1.0000x reference)
#include <cuda_runtime.h>
#include <cuda_bf16.h>

// BodyKinematics tree FK. B=4096, N=256, E=255.
// Round 8: R5 structure (pack prepass + g_tip planes, 1 batch/CTA) with
// stride-4 smem (row3 materialized -> pure-copy output), warp-local top
// levels, hoisted per-thread level, 6 full barriers.

#define NN 256
#define EE 255
#define PI_F 3.14159265358979f

__device__ float4 g_tip[3 * EE];   // [row][edge] planes, lane-coalesced reads

__global__ void pack_kernel(const float* __restrict__ tip) {
    const int j = blockIdx.x * blockDim.x + threadIdx.x;   // float4 index in (E,4,4)
    if (j < EE * 4) {
        const int e = j >> 2, row = j & 3;
        const float4 v = ((const float4*)tip)[j];
        if (row < 3) g_tip[row * EE + e] = v;
    }
}

__device__ __forceinline__ float ftanh(float x) {
    float ax = fabsf(x);
    float t = __expf(2.0f * ax);
    float r = __fdividef(t - 1.0f, t + 1.0f);
    r = ax > 40.0f ? 1.0f : r;
    return copysignf(r, x);
}

// world_row = P.x*L0 + P.y*L1 + P.z*L2 (+ P.w in translation slot)
__device__ __forceinline__ float4 aff(float4 P, float4 L0, float4 L1, float4 L2) {
    float4 w;
    w.x = fmaf(P.x, L0.x, fmaf(P.y, L1.x, P.z * L2.x));
    w.y = fmaf(P.x, L0.y, fmaf(P.y, L1.y, P.z * L2.y));
    w.z = fmaf(P.x, L0.z, fmaf(P.y, L1.z, P.z * L2.z));
    w.w = fmaf(P.x, L0.w, fmaf(P.y, L1.w, fmaf(P.z, L2.w, P.w)));
    return w;
}

__global__ __launch_bounds__(256) void fk_kernel(
    const float* __restrict__ la,    // (B, 3E)
    float* __restrict__ out)         // (B, N, 4, 4)
{
    // Full 4x4 worlds, node-major: S[4*node + row]. 16 KB. Output phase is a
    // straight contiguous copy S[j] -> out[j].
    __shared__ float4 S[NN * 4];

    const int b = blockIdx.x;
    const int t = threadIdx.x;

    float4 L0, L1, L2;   // local affine rows for node t+1 (edge t)

    if (t < EE) {
        const float* lap = la + (size_t)b * (3 * EE) + 3 * t;
        const float tha = PI_F * ftanh(lap[0]);
        const float thb = PI_F * ftanh(lap[1]);
        const float thc = PI_F * ftanh(lap[2]);

        float sa, ca, sb, cb, sc, cc;
        __sincosf(tha, &sa, &ca);
        __sincosf(thb, &sb, &cb);
        __sincosf(thc, &sc, &cc);

        // M = Rx(a) * Ry(b) * Rz(c)
        float M[9];
        M[0] = cb * cc;
        M[1] = -cb * sc;
        M[2] = sb;
        M[3] = fmaf(sa * sb, cc, ca * sc);
        M[4] = fmaf(-sa * sb, sc, ca * cc);
        M[5] = -sa * cb;
        M[6] = fmaf(-ca * sb, cc, sa * sc);
        M[7] = fmaf(ca * sb, sc, sa * cc);
        M[8] = ca * cb;

        const float4 T0 = g_tip[t];
        const float4 T1 = g_tip[EE + t];
        const float4 T2 = g_tip[2 * EE + t];
        #define MT(r, D)                                                        \
            D.x = fmaf(M[3*r], T0.x, fmaf(M[3*r+1], T1.x, M[3*r+2] * T2.x));    \
            D.y = fmaf(M[3*r], T0.y, fmaf(M[3*r+1], T1.y, M[3*r+2] * T2.y));    \
            D.z = fmaf(M[3*r], T0.z, fmaf(M[3*r+1], T1.z, M[3*r+2] * T2.z));    \
            D.w = fmaf(M[3*r], T0.w, fmaf(M[3*r+1], T1.w, M[3*r+2] * T2.w));
        MT(0, L0) MT(1, L1) MT(2, L2)
        #undef MT
    }

    // Constant row 3 of node t (written once, survives all phases).
    S[4 * t + 3] = make_float4(0.f, 0.f, 0.f, 1.f);
    // Root identity (node 0) by thread 255.
    if (t == EE) {
        S[0] = make_float4(1.f, 0.f, 0.f, 0.f);
        S[1] = make_float4(0.f, 1.f, 0.f, 0.f);
        S[2] = make_float4(0.f, 0.f, 1.f, 0.f);
    }
    // Level 1: nodes 1,2 world = local.
    if (t < 2) {
        const int q = 4 * (t + 1);
        S[q] = L0; S[q + 1] = L1; S[q + 2] = L2;
    }

    // Per-thread constants: node n = t+1, its single active level, offsets.
    const int lvl = (t < EE) ? (31 - __clz(t + 2)) : 0;   // level of node t+1
    const int i4  = 4 * t + 4;            // own node base
    const int p4  = (t >> 1) * 4;         // parent node base
    __syncthreads();

    #define STEP() {                                                  \
        const float4 P0 = S[p4], P1 = S[p4 + 1], P2 = S[p4 + 2];      \
        S[i4]     = aff(P0, L0, L1, L2);                              \
        S[i4 + 1] = aff(P1, L0, L1, L2);                              \
        S[i4 + 2] = aff(P2, L0, L1, L2); }

    // Levels 2-4 (nodes 3..30) live entirely in warp 0.
    if (t < 32) {
        if (lvl == 2) STEP();
        __syncwarp();
        if (lvl == 3) STEP();
        __syncwarp();
        if (lvl == 4) STEP();
    }
    __syncthreads();
    if (lvl == 5) STEP();
    __syncthreads();
    if (lvl == 6) STEP();
    __syncthreads();
    if (lvl == 7) STEP();
    __syncthreads();
    if (lvl == 8) STEP();
    __syncthreads();
    #undef STEP

    // Output: pure contiguous copy of the 16 KB block, 4 rounds.
    float4* o = (float4*)(out + (size_t)b * NN * 16);
    #pragma unroll
    for (int k = 0; k < 4; ++k) {
        const int j = k * NN + t;
        o[j] = S[j];
    }
}

extern "C" void kernel_launch(void* const* d_in, const int* in_sizes, int n_in,
                              void* d_out, int out_size) {
    const float* la  = (const float*)d_in[0];
    const float* tip = (const float*)d_in[1];
    float* out = (float*)d_out;

    const int B = in_sizes[0] / (3 * EE);
    pack_kernel<<<4, 256>>>(tip);
    fk_kernel<<<B, NN>>>(la, out);
}

// round 9
// speedup vs baseline: 1.2191x; 1.2191x over previous
#include <cuda_runtime.h>
#include <cuda_bf16.h>

// BodyKinematics tree FK. B=4096, N=256, E=255.
// Round 9: R5 verbatim (stride-3 smem, pack prepass, coalesced output) plus
// two layout-neutral trims: hoisted per-thread level + warp-local levels 2-4
// (syncwarp) with level 1 seeded from locals. 6 full barriers instead of 8.

#define NN 256
#define EE 255
#define PI_F 3.14159265358979f

__device__ float4 g_tip[3 * EE];   // [row][edge] planes, lane-coalesced reads

__global__ void pack_kernel(const float* __restrict__ tip) {
    const int j = blockIdx.x * blockDim.x + threadIdx.x;   // float4 index in (E,4,4)
    if (j < EE * 4) {
        const int e = j >> 2, row = j & 3;
        const float4 v = ((const float4*)tip)[j];
        if (row < 3) g_tip[row * EE + e] = v;
    }
}

__device__ __forceinline__ float ftanh(float x) {
    float ax = fabsf(x);
    float t = __expf(2.0f * ax);
    float r = __fdividef(t - 1.0f, t + 1.0f);
    r = ax > 40.0f ? 1.0f : r;
    return copysignf(r, x);
}

// world_row = P.x*L0 + P.y*L1 + P.z*L2 (+ P.w in translation slot)
__device__ __forceinline__ float4 aff(float4 P, float4 L0, float4 L1, float4 L2) {
    float4 w;
    w.x = fmaf(P.x, L0.x, fmaf(P.y, L1.x, P.z * L2.x));
    w.y = fmaf(P.x, L0.y, fmaf(P.y, L1.y, P.z * L2.y));
    w.z = fmaf(P.x, L0.z, fmaf(P.y, L1.z, P.z * L2.z));
    w.w = fmaf(P.x, L0.w, fmaf(P.y, L1.w, fmaf(P.z, L2.w, P.w)));
    return w;
}

__global__ __launch_bounds__(256) void fk_kernel(
    const float* __restrict__ la,    // (B, 3E)
    float* __restrict__ out)         // (B, N, 4, 4)
{
    // World affines: S[node*3 + row]. Stride-3 float4 granules (48 B/node,
    // coprime with banks) -> conflict-free LDS.128/STS.128. 12 KB.
    __shared__ float4 S[NN * 3];

    const int b = blockIdx.x;
    const int t = threadIdx.x;

    float4 L0, L1, L2;   // local affine rows for node t+1 (edge t)

    if (t < EE) {
        const float* lap = la + (size_t)b * (3 * EE) + 3 * t;
        const float tha = PI_F * ftanh(lap[0]);
        const float thb = PI_F * ftanh(lap[1]);
        const float thc = PI_F * ftanh(lap[2]);

        float sa, ca, sb, cb, sc, cc;
        __sincosf(tha, &sa, &ca);
        __sincosf(thb, &sb, &cb);
        __sincosf(thc, &sc, &cc);

        // M = Rx(a) * Ry(b) * Rz(c)
        float M[9];
        M[0] = cb * cc;
        M[1] = -cb * sc;
        M[2] = sb;
        M[3] = fmaf(sa * sb, cc, ca * sc);
        M[4] = fmaf(-sa * sb, sc, ca * cc);
        M[5] = -sa * cb;
        M[6] = fmaf(-ca * sb, cc, sa * sc);
        M[7] = fmaf(ca * sb, sc, sa * cc);
        M[8] = ca * cb;

        const float4 T0 = g_tip[t];
        const float4 T1 = g_tip[EE + t];
        const float4 T2 = g_tip[2 * EE + t];
        #define MT(r, D)                                                        \
            D.x = fmaf(M[3*r], T0.x, fmaf(M[3*r+1], T1.x, M[3*r+2] * T2.x));    \
            D.y = fmaf(M[3*r], T0.y, fmaf(M[3*r+1], T1.y, M[3*r+2] * T2.y));    \
            D.z = fmaf(M[3*r], T0.z, fmaf(M[3*r+1], T1.z, M[3*r+2] * T2.z));    \
            D.w = fmaf(M[3*r], T0.w, fmaf(M[3*r+1], T1.w, M[3*r+2] * T2.w));
        MT(0, L0) MT(1, L1) MT(2, L2)
        #undef MT
    }

    // Seeds: root identity (thread 255); nodes 1,2 world = local (level 1).
    if (t == EE) {
        S[0] = make_float4(1.f, 0.f, 0.f, 0.f);
        S[1] = make_float4(0.f, 1.f, 0.f, 0.f);
        S[2] = make_float4(0.f, 0.f, 1.f, 0.f);
    }
    if (t < 2) {
        const int q = 3 * (t + 1);
        S[q] = L0; S[q + 1] = L1; S[q + 2] = L2;
    }

    // Per-thread constants: node n = t+1, its single active level, offsets.
    const int lvl = (t < EE) ? (31 - __clz(t + 2)) : 0;   // level of node t+1
    const int i3  = 3 * (t + 1);          // own node base
    const int p3  = 3 * (t >> 1);         // parent node base ((n-1)>>1)
    __syncthreads();

    #define STEP() {                                                  \
        const float4 P0 = S[p3], P1 = S[p3 + 1], P2 = S[p3 + 2];      \
        S[i3]     = aff(P0, L0, L1, L2);                              \
        S[i3 + 1] = aff(P1, L0, L1, L2);                              \
        S[i3 + 2] = aff(P2, L0, L1, L2); }

    // Levels 2-4 (nodes 3..30 == threads 2..29) live entirely in warp 0.
    if (t < 32) {
        if (lvl == 2) STEP();
        __syncwarp();
        if (lvl == 3) STEP();
        __syncwarp();
        if (lvl == 4) STEP();
    }
    __syncthreads();
    if (lvl == 5) STEP();
    __syncthreads();
    if (lvl == 6) STEP();
    __syncthreads();
    if (lvl == 7) STEP();
    __syncthreads();
    if (lvl == 8) STEP();
    __syncthreads();
    #undef STEP

    // Coalesced output: CTA writes its 16KB block in 4 contiguous rounds.
    float4* o = (float4*)(out + (size_t)b * NN * 16);
    const float4 r3 = make_float4(0.f, 0.f, 0.f, 1.f);
    #pragma unroll
    for (int k = 0; k < 4; ++k) {
        const int j = k * NN + t;
        const int node = j >> 2, row = j & 3;
        o[j] = (row < 3) ? S[3 * node + row] : r3;
    }
}

extern "C" void kernel_launch(void* const* d_in, const int* in_sizes, int n_in,
                              void* d_out, int out_size) {
    const float* la  = (const float*)d_in[0];
    const float* tip = (const float*)d_in[1];
    float* out = (float*)d_out;

    const int B = in_sizes[0] / (3 * EE);
    pack_kernel<<<4, 256>>>(tip);
    fk_kernel<<<B, NN>>>(la, out);
}